// round 16
// baseline (speedup 1.0000x reference)
#include <cuda_runtime.h>
#include <cuda_fp16.h>
#include <mma.h>

using namespace nvcuda;

#define NMAX 50000
#define NPAD 50176          // 392*128 padding so GEMM tiles stay in-bounds
#define EMAX 1000000
#define HD   128
#define BPAD 136            // padded smem row (halves): conflict-free B LDSM
#define APAD 24             // padded A slice row (halves): 48B rows, 16B-aligned

// ---------------- device scratch (no allocation allowed) ----------------
// g_deg is zero at module load and re-zeroed by k_tail at the end of every
// launch, so each replay starts clean. g_ct reset by k_front (prior launch drained).
__device__ __align__(16) __half g_x[NPAD * HD];       // activations x~ (fp16; padding stays 0)
__device__ __align__(16) __half g_hs[NPAD * HD];      // messages hs = x~ @ W (fp16)
__device__ __align__(16) __half g_Bh3[3 * HD * HD];   // weight splits hi (layers 1..3)
__device__ __align__(16) __half g_Bl3[3 * HD * HD];   // weight splits lo
__device__ __align__(16) float  g_s1[NMAX * 3 + 4];
__device__ __align__(16) float  g_dis[NPAD];
__device__ __align__(16) int    g_deg[NMAX];
__device__ __align__(16) int    g_rowptr[NMAX + 1];
__device__ __align__(16) int    g_cursor[NMAX];
__device__ __align__(16) int    g_col[EMAX];
__device__ __align__(16) int    g_bsum[64];
__device__ int g_ct[2];

// ---------------- inline edge dtype detection ----------------
__device__ __forceinline__ int edges_is64(const int* __restrict__ w) {
    return (w[1] | w[3] | w[5] | w[7]) == 0;
}

// fast silu (MUFU.RCP path; rel err ~2^-21)
__device__ __forceinline__ float fsilu(float v) {
    return __fdividef(v, 1.0f + __expf(-v));
}

// ---------------- cp.async helpers ----------------
__device__ __forceinline__ void cp_async16(void* smem_dst, const void* gmem_src) {
    unsigned sa = (unsigned)__cvta_generic_to_shared(smem_dst);
    asm volatile("cp.async.ca.shared.global [%0], [%1], 16;" :: "r"(sa), "l"(gmem_src));
}
__device__ __forceinline__ void cp_async_commit() {
    asm volatile("cp.async.commit_group;");
}
template <int N>
__device__ __forceinline__ void cp_async_wait() {
    asm volatile("cp.async.wait_group %0;" :: "n"(N));
}

// ---------------- front: counter reset + weight splits + degree count ----------
__global__ void k_front(const int* __restrict__ w, const float* __restrict__ W1,
                        const float* __restrict__ W2, const float* __restrict__ W3,
                        int E) {
    int i = blockIdx.x * blockDim.x + threadIdx.x;
    if (i < 2) g_ct[i] = 0;
    if (i < 3 * HD * HD) {
        int l = i / (HD * HD), j = i - l * (HD * HD);
        const float* W = (l == 0) ? W1 : (l == 1) ? W2 : W3;
        float v = W[j];
        __half h = __float2half_rn(v);
        g_Bh3[i] = h;
        g_Bl3[i] = __float2half_rn(v - __half2float(h));
    }
    if (i < E) {
        int d = edges_is64(w) ? w[2 * E + 2 * i] : w[E + i];
        atomicAdd(&g_deg[d], 1);
    }
}

// ---------------- fused single-pass scan (grid co-resident: 49 blocks) ----------
__global__ __launch_bounds__(1024) void k_scan(const float* __restrict__ pos, int n) {
    __shared__ int s[1024];
    __shared__ int s_off;
    int tid = threadIdx.x;
    int i = blockIdx.x * 1024 + tid;
    int v = (i < n) ? g_deg[i] : 0;
    if (i < n) {
        float d = rsqrtf((float)(v + 1));   // +1 self loop
        g_dis[i] = d;
        g_s1[3 * i + 0] = pos[3 * i + 0] * d;
        g_s1[3 * i + 1] = pos[3 * i + 1] * d;
        g_s1[3 * i + 2] = pos[3 * i + 2] * d;
    }
    s[tid] = v;
    __syncthreads();
    for (int off = 1; off < 1024; off <<= 1) {
        int t = (tid >= off) ? s[tid - off] : 0;
        __syncthreads();
        s[tid] += t;
        __syncthreads();
    }
    if (tid == 1023) {
        g_bsum[blockIdx.x] = s[1023];
        __threadfence();
        atomicAdd(&g_ct[0], 1);
    }
    if (tid == 0) {
        while (((volatile int*)&g_ct[0])[0] < gridDim.x) {}
    }
    __syncthreads();
    __threadfence();
    if (tid < 32) {
        int l = tid, bid = blockIdx.x;
        int pv = (l < bid) ? g_bsum[l] : 0;
        if (l + 32 < bid) pv += g_bsum[l + 32];
        for (int off = 16; off; off >>= 1) pv += __shfl_xor_sync(0xFFFFFFFF, pv, off);
        if (l == 0) s_off = pv;
    }
    __syncthreads();
    int off = s_off;
    if (i < n) {
        int rv = s[tid] + off;
        g_rowptr[i + 1] = rv;
        if (i + 1 < n) g_cursor[i + 1] = rv;
    }
    if (i == 0) { g_rowptr[0] = 0; g_cursor[0] = 0; }
}

// CSR fill, decoding edges in place
__global__ void k_fill(const int* __restrict__ w, int E) {
    int i = blockIdx.x * blockDim.x + threadIdx.x;
    if (i >= E) return;
    int s, d;
    if (edges_is64(w)) {
        s = w[2 * i];
        d = w[2 * E + 2 * i];
    } else {
        s = w[i];
        d = w[E + i];
    }
    int p = atomicAdd(&g_cursor[d], 1);
    g_col[p] = s;
}

// ---------------- fused layer 0: 16 lanes per node ----------------
__global__ __launch_bounds__(256) void k_layer0(const float* __restrict__ s1,
                                                const float* __restrict__ W0,
                                                const float* __restrict__ b0,
                                                __half* __restrict__ out, int n) {
    __shared__ float sw[3 * HD];
    __shared__ float sb[HD];
    int t = threadIdx.x;
    for (int i = t; i < 3 * HD; i += 256) sw[i] = W0[i];
    if (t < HD) sb[t] = b0[t];
    __syncthreads();
    int gtid = blockIdx.x * 256 + t;
    int node = gtid >> 4;
    int l16 = gtid & 15;
    if (node >= n) return;
    int s = g_rowptr[node], e = g_rowptr[node + 1];
    float a0 = 0.f, a1 = 0.f, a2 = 0.f;
    for (int i = s + l16; i < e; i += 16) {
        int c = g_col[i];
        a0 += s1[3 * c + 0];
        a1 += s1[3 * c + 1];
        a2 += s1[3 * c + 2];
    }
#pragma unroll
    for (int off = 8; off; off >>= 1) {
        a0 += __shfl_xor_sync(0xFFFFFFFF, a0, off);
        a1 += __shfl_xor_sync(0xFFFFFFFF, a1, off);
        a2 += __shfl_xor_sync(0xFFFFFFFF, a2, off);
    }
    a0 += s1[3 * node + 0];            // self loop
    a1 += s1[3 * node + 1];
    a2 += s1[3 * node + 2];
    float d = g_dis[node];
    a0 *= d; a1 *= d; a2 *= d;
    __half2 o[4];
#pragma unroll
    for (int q = 0; q < 4; q++) {
        int j0 = l16 * 8 + 2 * q;
        float v0 = a0 * sw[j0] + a1 * sw[HD + j0] + a2 * sw[2 * HD + j0] + sb[j0];
        float v1 = a0 * sw[j0 + 1] + a1 * sw[HD + j0 + 1] + a2 * sw[2 * HD + j0 + 1] + sb[j0 + 1];
        o[q] = __floats2half2_rn(d * fsilu(v0), d * fsilu(v1));
    }
    ((uint4*)out)[node * 16 + l16] = *(uint4*)o;
}

// ---------------- tensor-core hidden GEMM: hs = x~ @ (Bh+Bl) ----------------
// B staged once per block; A k-slices cp.async double-buffered; 1 sync/iteration.
__global__ __launch_bounds__(256, 2) void k_gemm128_tc(const __half* __restrict__ X,
                                                       const __half* __restrict__ Bh,
                                                       const __half* __restrict__ Bl,
                                                       __half* __restrict__ Hout) {
    extern __shared__ __align__(16) __half smem[];
    __half* sBh = smem;                       // [128][BPAD]
    __half* sBl = smem + 128 * BPAD;          // [128][BPAD]
    __half* sA  = smem + 2 * 128 * BPAD;      // [2][128][APAD]

    int t = threadIdx.x;
    int warp = t >> 5;
    int lane = t & 31;
    int wm = warp >> 1;
    int wn = warp & 1;
    int m0 = blockIdx.x * 128;

    int arow = t >> 1;
    int ac8 = (t & 1) * 8;
    const __half* ag = X + (m0 + arow) * HD + ac8;

    cp_async16(sA + arow * APAD + ac8, ag);   // slice 0 -> buf 0
    cp_async_commit();

#pragma unroll
    for (int q = 0; q < 8; q++) {
        int idx = t + q * 256;
        int row = idx >> 4;
        int c16 = (idx & 15) * 8;
        *(uint4*)(sBh + row * BPAD + c16) = *(const uint4*)(Bh + row * HD + c16);
        *(uint4*)(sBl + row * BPAD + c16) = *(const uint4*)(Bl + row * HD + c16);
    }

    wmma::fragment<wmma::accumulator, 16, 16, 16, float> c[2][4];
#pragma unroll
    for (int i = 0; i < 2; i++)
#pragma unroll
        for (int j = 0; j < 4; j++) wmma::fill_fragment(c[i][j], 0.0f);

#pragma unroll
    for (int ks = 0; ks < 8; ks++) {
        // sync at top: all warps done computing iteration ks-1 (frees buf (ks+1)&1);
        // on ks=0 it also makes the B staging visible.
        __syncthreads();
        if (ks < 7) {
            cp_async16(sA + ((ks + 1) & 1) * 128 * APAD + arow * APAD + ac8,
                       ag + (ks + 1) * 16);
            cp_async_commit();
            cp_async_wait<1>();    // slice ks complete
        } else {
            cp_async_wait<0>();
        }
        // slice ks was written by THIS thread's cp.async; fragment loads read other
        // threads' data -> need visibility: the wait above drains this thread's
        // copies; cross-thread visibility was established by the sync at top of the
        // NEXT... (fragment reads happen after all threads passed wait) — enforce:
        __syncwarp();
        // NOTE: cross-thread ordering for slice ks: every thread issued its slice-ks
        // copy before the top sync of iteration ks, and waits on it above before any
        // thread reads. A second barrier is still required so no warp reads before
        // every thread's wait retired:
        __syncthreads();

        const __half* sAc = sA + (ks & 1) * 128 * APAD;
        int k0 = ks * 16;
        wmma::fragment<wmma::matrix_a, 16, 16, 16, __half, wmma::row_major> a[2];
#pragma unroll
        for (int i = 0; i < 2; i++)
            wmma::load_matrix_sync(a[i], sAc + (wm * 32 + i * 16) * APAD, APAD);
#pragma unroll
        for (int j = 0; j < 4; j++) {
            wmma::fragment<wmma::matrix_b, 16, 16, 16, __half, wmma::row_major> bH, bL;
            wmma::load_matrix_sync(bH, sBh + k0 * BPAD + wn * 64 + j * 16, BPAD);
            wmma::load_matrix_sync(bL, sBl + k0 * BPAD + wn * 64 + j * 16, BPAD);
            wmma::mma_sync(c[0][j], a[0], bH, c[0][j]);
            wmma::mma_sync(c[1][j], a[1], bH, c[1][j]);
            wmma::mma_sync(c[0][j], a[0], bL, c[0][j]);
            wmma::mma_sync(c[1][j], a[1], bL, c[1][j]);
        }
    }

    // epilogue: fp32 fragment -> fp16 gmem via smem bounce
    __syncthreads();
    float* sOut = (float*)smem + warp * 256;
#pragma unroll
    for (int i = 0; i < 2; i++)
#pragma unroll
        for (int j = 0; j < 4; j++) {
            wmma::store_matrix_sync(sOut, c[i][j], 16, wmma::mem_row_major);
            __syncwarp();
            int r = lane >> 1;
            int c8 = (lane & 1) * 8;
            const float* srcp = sOut + r * 16 + c8;
            __half2 o[4];
#pragma unroll
            for (int q = 0; q < 4; q++)
                o[q] = __floats2half2_rn(srcp[2 * q], srcp[2 * q + 1]);
            __half* dst = Hout + (m0 + wm * 32 + i * 16 + r) * HD + wn * 64 + j * 16 + c8;
            *(uint4*)dst = *(uint4*)o;
            __syncwarp();
        }
}

// ---------------- 128-wide aggregation: 16 lanes per node, 8-edge unroll ----------------
__global__ void k_agg128(const __half* __restrict__ hs, const float* __restrict__ bias,
                         __half* __restrict__ out, int n) {
    int gtid = blockIdx.x * blockDim.x + threadIdx.x;
    int node = gtid >> 4;
    int l16 = gtid & 15;
    if (node >= n) return;
    const uint4* hs4 = (const uint4*)hs;
    float acc[8];
    {
        uint4 u = hs4[node * 16 + l16];    // self loop
        __half2* hp = (__half2*)&u;
#pragma unroll
        for (int q = 0; q < 4; q++) {
            float2 f = __half22float2(hp[q]);
            acc[2 * q] = f.x; acc[2 * q + 1] = f.y;
        }
    }
    int s = g_rowptr[node], e = g_rowptr[node + 1];
    int i = s;
    int head = (s + 3) & ~3;
    if (head > e) head = e;
    for (; i < head; i++) {
        int c = g_col[i];
        uint4 v = hs4[c * 16 + l16];
        __half2* p = (__half2*)&v;
#pragma unroll
        for (int q = 0; q < 4; q++) {
            float2 f = __half22float2(p[q]);
            acc[2 * q] += f.x; acc[2 * q + 1] += f.y;
        }
    }
    for (; i + 8 <= e; i += 8) {
        int4 ca = *(const int4*)(g_col + i);
        int4 cb = *(const int4*)(g_col + i + 4);
        uint4 v0 = hs4[ca.x * 16 + l16];
        uint4 v1 = hs4[ca.y * 16 + l16];
        uint4 v2 = hs4[ca.z * 16 + l16];
        uint4 v3 = hs4[ca.w * 16 + l16];
        uint4 v4 = hs4[cb.x * 16 + l16];
        uint4 v5 = hs4[cb.y * 16 + l16];
        uint4 v6 = hs4[cb.z * 16 + l16];
        uint4 v7 = hs4[cb.w * 16 + l16];
        __half2* p0 = (__half2*)&v0; __half2* p1 = (__half2*)&v1;
        __half2* p2 = (__half2*)&v2; __half2* p3 = (__half2*)&v3;
        __half2* p4 = (__half2*)&v4; __half2* p5 = (__half2*)&v5;
        __half2* p6 = (__half2*)&v6; __half2* p7 = (__half2*)&v7;
#pragma unroll
        for (int q = 0; q < 4; q++) {
            __half2 t01 = __hadd2(p0[q], p1[q]);
            __half2 t23 = __hadd2(p2[q], p3[q]);
            __half2 t45 = __hadd2(p4[q], p5[q]);
            __half2 t67 = __hadd2(p6[q], p7[q]);
            float2 f01 = __half22float2(t01);
            float2 f23 = __half22float2(t23);
            float2 f45 = __half22float2(t45);
            float2 f67 = __half22float2(t67);
            acc[2 * q]     += (f01.x + f23.x) + (f45.x + f67.x);
            acc[2 * q + 1] += (f01.y + f23.y) + (f45.y + f67.y);
        }
    }
    for (; i + 4 <= e; i += 4) {
        int4 cc = *(const int4*)(g_col + i);
        uint4 v0 = hs4[cc.x * 16 + l16];
        uint4 v1 = hs4[cc.y * 16 + l16];
        uint4 v2 = hs4[cc.z * 16 + l16];
        uint4 v3 = hs4[cc.w * 16 + l16];
        __half2* p0 = (__half2*)&v0; __half2* p1 = (__half2*)&v1;
        __half2* p2 = (__half2*)&v2; __half2* p3 = (__half2*)&v3;
#pragma unroll
        for (int q = 0; q < 4; q++) {
            __half2 t01 = __hadd2(p0[q], p1[q]);
            __half2 t23 = __hadd2(p2[q], p3[q]);
            float2 f01 = __half22float2(t01);
            float2 f23 = __half22float2(t23);
            acc[2 * q]     += f01.x + f23.x;
            acc[2 * q + 1] += f01.y + f23.y;
        }
    }
    for (; i < e; i++) {
        int c = g_col[i];
        uint4 v = hs4[c * 16 + l16];
        __half2* p = (__half2*)&v;
#pragma unroll
        for (int q = 0; q < 4; q++) {
            float2 f = __half22float2(p[q]);
            acc[2 * q] += f.x; acc[2 * q + 1] += f.y;
        }
    }
    float d = g_dis[node];
    const float4* b4 = (const float4*)bias;
    float4 b0 = b4[l16 * 2], b1 = b4[l16 * 2 + 1];
    float bb[8] = {b0.x, b0.y, b0.z, b0.w, b1.x, b1.y, b1.z, b1.w};
    __half2 o[4];
#pragma unroll
    for (int q = 0; q < 4; q++) {
        float r0 = acc[2 * q] * d + bb[2 * q];
        float r1 = acc[2 * q + 1] * d + bb[2 * q + 1];
        o[q] = __floats2half2_rn(d * fsilu(r0), d * fsilu(r1));
    }
    ((uint4*)out)[node * 16 + l16] = *(uint4*)o;
}

// ---------------- fused tail: hs3 = x~ @ W4, grid-sync, 3-wide agg -> out ---------
// Phase 2 also re-zeroes g_deg for the next launch.
#define TAIL_BLOCKS 592
__global__ __launch_bounds__(256) void k_tail(const __half* __restrict__ X,
                                              const float* __restrict__ W4,
                                              const float* __restrict__ bias,
                                              float* __restrict__ s1,
                                              float* __restrict__ out, int n) {
    int t = threadIdx.x;
    int lane = t & 31;
    int nwarps = TAIL_BLOCKS * 8;
    for (int node = (blockIdx.x * 256 + t) >> 5; node < n; node += nwarps) {
        uint2 u = ((const uint2*)X)[node * 32 + lane];
        float2 p0 = __half22float2(*(__half2*)&u.x);
        float2 p1 = __half22float2(*(__half2*)&u.y);
        int k = lane * 4;
        float a0 = p0.x * W4[(k + 0) * 3 + 0] + p0.y * W4[(k + 1) * 3 + 0] +
                   p1.x * W4[(k + 2) * 3 + 0] + p1.y * W4[(k + 3) * 3 + 0];
        float a1 = p0.x * W4[(k + 0) * 3 + 1] + p0.y * W4[(k + 1) * 3 + 1] +
                   p1.x * W4[(k + 2) * 3 + 1] + p1.y * W4[(k + 3) * 3 + 1];
        float a2 = p0.x * W4[(k + 0) * 3 + 2] + p0.y * W4[(k + 1) * 3 + 2] +
                   p1.x * W4[(k + 2) * 3 + 2] + p1.y * W4[(k + 3) * 3 + 2];
        for (int off = 16; off; off >>= 1) {
            a0 += __shfl_xor_sync(0xFFFFFFFF, a0, off);
            a1 += __shfl_xor_sync(0xFFFFFFFF, a1, off);
            a2 += __shfl_xor_sync(0xFFFFFFFF, a2, off);
        }
        if (lane == 0) {
            s1[node * 3 + 0] = a0;
            s1[node * 3 + 1] = a1;
            s1[node * 3 + 2] = a2;
        }
    }
    __syncthreads();
    if (t == 0) {
        __threadfence();
        atomicAdd(&g_ct[1], 1);
        while (((volatile int*)&g_ct[1])[0] < TAIL_BLOCKS) {}
    }
    __syncthreads();
    __threadfence();
    float bb0 = bias[0], bb1 = bias[1], bb2 = bias[2];
    for (int node = blockIdx.x * 256 + t; node < n; node += TAIL_BLOCKS * 256) {
        float a0 = s1[node * 3 + 0], a1 = s1[node * 3 + 1], a2 = s1[node * 3 + 2];
        int s = g_rowptr[node], e = g_rowptr[node + 1];
        for (int i = s; i < e; i++) {
            int c = g_col[i];
            a0 += s1[3 * c + 0];
            a1 += s1[3 * c + 1];
            a2 += s1[3 * c + 2];
        }
        float d = g_dis[node];
        out[node * 3 + 0] = a0 * d + bb0;
        out[node * 3 + 1] = a1 * d + bb1;
        out[node * 3 + 2] = a2 * d + bb2;
        g_deg[node] = 0;                 // clean for next launch
    }
}

// ---------------- host launch ----------------
extern "C" void kernel_launch(void* const* d_in, const int* in_sizes, int n_in,
                              void* d_out, int out_size) {
    const float* pos = (const float*)d_in[0];
    const int* ei_words = (const int*)d_in[1];
    const float* W[5]; const float* B[5];
    for (int l = 0; l < 5; l++) {
        W[l] = (const float*)d_in[2 + 2 * l];
        B[l] = (const float*)d_in[3 + 2 * l];
    }
    int N = in_sizes[0] / 3;        // 50000
    int E = in_sizes[1] / 2;        // 1000000

    __half *xbuf, *hsbuf, *bh3, *bl3;
    float *s1;
    cudaGetSymbolAddress((void**)&xbuf, g_x);
    cudaGetSymbolAddress((void**)&hsbuf, g_hs);
    cudaGetSymbolAddress((void**)&bh3, g_Bh3);
    cudaGetSymbolAddress((void**)&bl3, g_Bl3);
    cudaGetSymbolAddress((void**)&s1, g_s1);

    int NB = (N + 1023) / 1024;     // 49
    const int GEMM_SMEM = (2 * 128 * BPAD + 2 * 128 * APAD) * 2;   // 81920 bytes

    static int smem_set = 0;
    if (!smem_set) {
        cudaFuncSetAttribute(k_gemm128_tc,
                             cudaFuncAttributeMaxDynamicSharedMemorySize, GEMM_SMEM);
        smem_set = 1;
    }

    // front: counters + weight splits + degree count (deg zeroed by prior k_tail)
    k_front<<<(E + 255) / 256, 256>>>(ei_words, W[1], W[2], W[3], E);

    // fused scan (rowptr/cursor/dis/s1), CSR fill
    k_scan<<<NB, 1024>>>(pos, N);
    k_fill<<<(E + 255) / 256, 256>>>(ei_words, E);

    // layer 0 (fused 3-wide agg + dense W0 + bias + silu + dis fold) -> fp16 x~
    k_layer0<<<(N * 16 + 255) / 256, 256>>>(s1, W[0], B[0], xbuf, N);

    // layers 1..3: TC GEMM then fp16 aggregation
    int gemm_blocks = NPAD / 128;            // 392
    int agg_blocks = (N * 16 + 255) / 256;   // 16 lanes per node
    for (int l = 1; l <= 3; l++) {
        k_gemm128_tc<<<gemm_blocks, 256, GEMM_SMEM>>>(xbuf, bh3 + (l - 1) * HD * HD,
                                                      bl3 + (l - 1) * HD * HD, hsbuf);
        k_agg128<<<agg_blocks, 256>>>(hsbuf, B[l], xbuf, N);
    }

    // fused tail: hs3 GEMM + grid sync + 3-wide aggregation -> out (+ deg re-zero)
    k_tail<<<TAIL_BLOCKS, 256>>>(xbuf, W[4], B[4], s1, (float*)d_out, N);
}

// round 17
// speedup vs baseline: 1.0335x; 1.0335x over previous
#include <cuda_runtime.h>
#include <cuda_fp16.h>
#include <mma.h>

using namespace nvcuda;

#define NMAX 50000
#define NPAD 50176          // 392*128 padding so GEMM tiles stay in-bounds
#define EMAX 1000000
#define HD   128
#define BPAD 136            // padded smem row (halves): conflict-free B LDSM
#define APAD 24             // padded A slice row (halves): 48B rows, 16B-aligned

// ---------------- device scratch (no allocation allowed) ----------------
// g_deg zero at module load; re-zeroed by k_tail each launch. g_ct reset by k_front.
__device__ __align__(16) __half g_x[NPAD * HD];       // activations x~ (fp16; padding stays 0)
__device__ __align__(16) __half g_hs[NPAD * HD];      // messages hs = x~ @ W (fp16)
__device__ __align__(16) __half g_Bh3[3 * HD * HD];   // weight splits hi (layers 1..3)
__device__ __align__(16) __half g_Bl3[3 * HD * HD];   // weight splits lo
__device__ __align__(16) float4 g_s1[NMAX];           // 3-wide scratch, float4 (w unused)
__device__ __align__(16) float  g_dis[NPAD];
__device__ __align__(16) int    g_deg[NMAX];
__device__ __align__(16) int    g_rowptr[NMAX + 1];
__device__ __align__(16) int    g_cursor[NMAX];
__device__ __align__(16) int    g_col[EMAX];
__device__ __align__(16) int    g_bsum[64];
__device__ int g_ct[2];

// ---------------- inline edge dtype detection ----------------
__device__ __forceinline__ int edges_is64(const int* __restrict__ w) {
    return (w[1] | w[3] | w[5] | w[7]) == 0;
}

// fast silu (MUFU.RCP path; rel err ~2^-21)
__device__ __forceinline__ float fsilu(float v) {
    return __fdividef(v, 1.0f + __expf(-v));
}

// ---------------- cp.async helpers ----------------
__device__ __forceinline__ void cp_async16(void* smem_dst, const void* gmem_src) {
    unsigned sa = (unsigned)__cvta_generic_to_shared(smem_dst);
    asm volatile("cp.async.ca.shared.global [%0], [%1], 16;" :: "r"(sa), "l"(gmem_src));
}
__device__ __forceinline__ void cp_async_commit() {
    asm volatile("cp.async.commit_group;");
}
template <int N>
__device__ __forceinline__ void cp_async_wait() {
    asm volatile("cp.async.wait_group %0;" :: "n"(N));
}

// ---------------- front: counter reset + weight splits + degree count ----------
__global__ void k_front(const int* __restrict__ w, const float* __restrict__ W1,
                        const float* __restrict__ W2, const float* __restrict__ W3,
                        int E) {
    int i = blockIdx.x * blockDim.x + threadIdx.x;
    if (i < 2) g_ct[i] = 0;
    if (i < 3 * HD * HD) {
        int l = i / (HD * HD), j = i - l * (HD * HD);
        const float* W = (l == 0) ? W1 : (l == 1) ? W2 : W3;
        float v = W[j];
        __half h = __float2half_rn(v);
        g_Bh3[i] = h;
        g_Bl3[i] = __float2half_rn(v - __half2float(h));
    }
    if (i < E) {
        int d = edges_is64(w) ? w[2 * E + 2 * i] : w[E + i];
        atomicAdd(&g_deg[d], 1);
    }
}

// ---------------- fused single-pass scan (grid co-resident: 49 blocks) ----------
__global__ __launch_bounds__(1024) void k_scan(const float* __restrict__ pos, int n) {
    __shared__ int s[1024];
    __shared__ int s_off;
    int tid = threadIdx.x;
    int i = blockIdx.x * 1024 + tid;
    int v = (i < n) ? g_deg[i] : 0;
    if (i < n) {
        float d = rsqrtf((float)(v + 1));   // +1 self loop
        g_dis[i] = d;
        g_s1[i] = make_float4(pos[3 * i + 0] * d, pos[3 * i + 1] * d,
                              pos[3 * i + 2] * d, 0.0f);
    }
    s[tid] = v;
    __syncthreads();
    for (int off = 1; off < 1024; off <<= 1) {
        int t = (tid >= off) ? s[tid - off] : 0;
        __syncthreads();
        s[tid] += t;
        __syncthreads();
    }
    if (tid == 1023) {
        g_bsum[blockIdx.x] = s[1023];
        __threadfence();
        atomicAdd(&g_ct[0], 1);
    }
    if (tid == 0) {
        while (((volatile int*)&g_ct[0])[0] < gridDim.x) {}
    }
    __syncthreads();
    __threadfence();
    if (tid < 32) {
        int l = tid, bid = blockIdx.x;
        int pv = (l < bid) ? g_bsum[l] : 0;
        if (l + 32 < bid) pv += g_bsum[l + 32];
        for (int off = 16; off; off >>= 1) pv += __shfl_xor_sync(0xFFFFFFFF, pv, off);
        if (l == 0) s_off = pv;
    }
    __syncthreads();
    int off = s_off;
    if (i < n) {
        int rv = s[tid] + off;
        g_rowptr[i + 1] = rv;
        if (i + 1 < n) g_cursor[i + 1] = rv;
    }
    if (i == 0) { g_rowptr[0] = 0; g_cursor[0] = 0; }
}

// CSR fill, decoding edges in place
__global__ void k_fill(const int* __restrict__ w, int E) {
    int i = blockIdx.x * blockDim.x + threadIdx.x;
    if (i >= E) return;
    int s, d;
    if (edges_is64(w)) {
        s = w[2 * i];
        d = w[2 * E + 2 * i];
    } else {
        s = w[i];
        d = w[E + i];
    }
    int p = atomicAdd(&g_cursor[d], 1);
    g_col[p] = s;
}

// ---------------- fused layer 0: 16 lanes per node, float4 gathers ----------------
__global__ __launch_bounds__(256) void k_layer0(const float* __restrict__ W0,
                                                const float* __restrict__ b0,
                                                __half* __restrict__ out, int n) {
    __shared__ float sw[3 * HD];
    __shared__ float sb[HD];
    int t = threadIdx.x;
    for (int i = t; i < 3 * HD; i += 256) sw[i] = W0[i];
    if (t < HD) sb[t] = b0[t];
    __syncthreads();
    int gtid = blockIdx.x * 256 + t;
    int node = gtid >> 4;
    int l16 = gtid & 15;
    if (node >= n) return;
    int s = g_rowptr[node], e = g_rowptr[node + 1];
    float a0 = 0.f, a1 = 0.f, a2 = 0.f;
    for (int i = s + l16; i < e; i += 16) {
        float4 v = g_s1[g_col[i]];
        a0 += v.x; a1 += v.y; a2 += v.z;
    }
#pragma unroll
    for (int off = 8; off; off >>= 1) {
        a0 += __shfl_xor_sync(0xFFFFFFFF, a0, off);
        a1 += __shfl_xor_sync(0xFFFFFFFF, a1, off);
        a2 += __shfl_xor_sync(0xFFFFFFFF, a2, off);
    }
    float4 self = g_s1[node];          // self loop
    a0 += self.x; a1 += self.y; a2 += self.z;
    float d = g_dis[node];
    a0 *= d; a1 *= d; a2 *= d;
    __half2 o[4];
#pragma unroll
    for (int q = 0; q < 4; q++) {
        int j0 = l16 * 8 + 2 * q;
        float v0 = a0 * sw[j0] + a1 * sw[HD + j0] + a2 * sw[2 * HD + j0] + sb[j0];
        float v1 = a0 * sw[j0 + 1] + a1 * sw[HD + j0 + 1] + a2 * sw[2 * HD + j0 + 1] + sb[j0 + 1];
        o[q] = __floats2half2_rn(d * fsilu(v0), d * fsilu(v1));
    }
    ((uint4*)out)[node * 16 + l16] = *(uint4*)o;
}

// ---------------- tensor-core hidden GEMM: hs = x~ @ (Bh+Bl) ----------------
__global__ __launch_bounds__(256, 2) void k_gemm128_tc(const __half* __restrict__ X,
                                                       const __half* __restrict__ Bh,
                                                       const __half* __restrict__ Bl,
                                                       __half* __restrict__ Hout) {
    extern __shared__ __align__(16) __half smem[];
    __half* sBh = smem;                       // [128][BPAD]
    __half* sBl = smem + 128 * BPAD;          // [128][BPAD]
    __half* sA  = smem + 2 * 128 * BPAD;      // [2][128][APAD]

    int t = threadIdx.x;
    int warp = t >> 5;
    int lane = t & 31;
    int wm = warp >> 1;
    int wn = warp & 1;
    int m0 = blockIdx.x * 128;

    int arow = t >> 1;
    int ac8 = (t & 1) * 8;
    const __half* ag = X + (m0 + arow) * HD + ac8;

    cp_async16(sA + arow * APAD + ac8, ag);   // slice 0 -> buf 0
    cp_async_commit();

#pragma unroll
    for (int q = 0; q < 8; q++) {
        int idx = t + q * 256;
        int row = idx >> 4;
        int c16 = (idx & 15) * 8;
        *(uint4*)(sBh + row * BPAD + c16) = *(const uint4*)(Bh + row * HD + c16);
        *(uint4*)(sBl + row * BPAD + c16) = *(const uint4*)(Bl + row * HD + c16);
    }

    wmma::fragment<wmma::accumulator, 16, 16, 16, float> c[2][4];
#pragma unroll
    for (int i = 0; i < 2; i++)
#pragma unroll
        for (int j = 0; j < 4; j++) wmma::fill_fragment(c[i][j], 0.0f);

#pragma unroll
    for (int ks = 0; ks < 8; ks++) {
        __syncthreads();
        if (ks < 7) {
            cp_async16(sA + ((ks + 1) & 1) * 128 * APAD + arow * APAD + ac8,
                       ag + (ks + 1) * 16);
            cp_async_commit();
            cp_async_wait<1>();
        } else {
            cp_async_wait<0>();
        }
        __syncthreads();

        const __half* sAc = sA + (ks & 1) * 128 * APAD;
        int k0 = ks * 16;
        wmma::fragment<wmma::matrix_a, 16, 16, 16, __half, wmma::row_major> a[2];
#pragma unroll
        for (int i = 0; i < 2; i++)
            wmma::load_matrix_sync(a[i], sAc + (wm * 32 + i * 16) * APAD, APAD);
#pragma unroll
        for (int j = 0; j < 4; j++) {
            wmma::fragment<wmma::matrix_b, 16, 16, 16, __half, wmma::row_major> bH, bL;
            wmma::load_matrix_sync(bH, sBh + k0 * BPAD + wn * 64 + j * 16, BPAD);
            wmma::load_matrix_sync(bL, sBl + k0 * BPAD + wn * 64 + j * 16, BPAD);
            wmma::mma_sync(c[0][j], a[0], bH, c[0][j]);
            wmma::mma_sync(c[1][j], a[1], bH, c[1][j]);
            wmma::mma_sync(c[0][j], a[0], bL, c[0][j]);
            wmma::mma_sync(c[1][j], a[1], bL, c[1][j]);
        }
    }

    // epilogue: fp32 fragment -> fp16 gmem via smem bounce
    __syncthreads();
    float* sOut = (float*)smem + warp * 256;
#pragma unroll
    for (int i = 0; i < 2; i++)
#pragma unroll
        for (int j = 0; j < 4; j++) {
            wmma::store_matrix_sync(sOut, c[i][j], 16, wmma::mem_row_major);
            __syncwarp();
            int r = lane >> 1;
            int c8 = (lane & 1) * 8;
            const float* srcp = sOut + r * 16 + c8;
            __half2 o[4];
#pragma unroll
            for (int q = 0; q < 4; q++)
                o[q] = __floats2half2_rn(srcp[2 * q], srcp[2 * q + 1]);
            __half* dst = Hout + (m0 + wm * 32 + i * 16 + r) * HD + wn * 64 + j * 16 + c8;
            *(uint4*)dst = *(uint4*)o;
            __syncwarp();
        }
}

// ---------------- 128-wide aggregation: 16 lanes per node, 8-edge unroll ----------------
__global__ void k_agg128(const __half* __restrict__ hs, const float* __restrict__ bias,
                         __half* __restrict__ out, int n) {
    int gtid = blockIdx.x * blockDim.x + threadIdx.x;
    int node = gtid >> 4;
    int l16 = gtid & 15;
    if (node >= n) return;
    const uint4* hs4 = (const uint4*)hs;
    float acc[8];
    {
        uint4 u = hs4[node * 16 + l16];    // self loop
        __half2* hp = (__half2*)&u;
#pragma unroll
        for (int q = 0; q < 4; q++) {
            float2 f = __half22float2(hp[q]);
            acc[2 * q] = f.x; acc[2 * q + 1] = f.y;
        }
    }
    int s = g_rowptr[node], e = g_rowptr[node + 1];
    int i = s;
    int head = (s + 3) & ~3;
    if (head > e) head = e;
    for (; i < head; i++) {
        int c = g_col[i];
        uint4 v = hs4[c * 16 + l16];
        __half2* p = (__half2*)&v;
#pragma unroll
        for (int q = 0; q < 4; q++) {
            float2 f = __half22float2(p[q]);
            acc[2 * q] += f.x; acc[2 * q + 1] += f.y;
        }
    }
    for (; i + 8 <= e; i += 8) {
        int4 ca = *(const int4*)(g_col + i);
        int4 cb = *(const int4*)(g_col + i + 4);
        uint4 v0 = hs4[ca.x * 16 + l16];
        uint4 v1 = hs4[ca.y * 16 + l16];
        uint4 v2 = hs4[ca.z * 16 + l16];
        uint4 v3 = hs4[ca.w * 16 + l16];
        uint4 v4 = hs4[cb.x * 16 + l16];
        uint4 v5 = hs4[cb.y * 16 + l16];
        uint4 v6 = hs4[cb.z * 16 + l16];
        uint4 v7 = hs4[cb.w * 16 + l16];
        __half2* p0 = (__half2*)&v0; __half2* p1 = (__half2*)&v1;
        __half2* p2 = (__half2*)&v2; __half2* p3 = (__half2*)&v3;
        __half2* p4 = (__half2*)&v4; __half2* p5 = (__half2*)&v5;
        __half2* p6 = (__half2*)&v6; __half2* p7 = (__half2*)&v7;
#pragma unroll
        for (int q = 0; q < 4; q++) {
            __half2 t01 = __hadd2(p0[q], p1[q]);
            __half2 t23 = __hadd2(p2[q], p3[q]);
            __half2 t45 = __hadd2(p4[q], p5[q]);
            __half2 t67 = __hadd2(p6[q], p7[q]);
            float2 f01 = __half22float2(t01);
            float2 f23 = __half22float2(t23);
            float2 f45 = __half22float2(t45);
            float2 f67 = __half22float2(t67);
            acc[2 * q]     += (f01.x + f23.x) + (f45.x + f67.x);
            acc[2 * q + 1] += (f01.y + f23.y) + (f45.y + f67.y);
        }
    }
    for (; i + 4 <= e; i += 4) {
        int4 cc = *(const int4*)(g_col + i);
        uint4 v0 = hs4[cc.x * 16 + l16];
        uint4 v1 = hs4[cc.y * 16 + l16];
        uint4 v2 = hs4[cc.z * 16 + l16];
        uint4 v3 = hs4[cc.w * 16 + l16];
        __half2* p0 = (__half2*)&v0; __half2* p1 = (__half2*)&v1;
        __half2* p2 = (__half2*)&v2; __half2* p3 = (__half2*)&v3;
#pragma unroll
        for (int q = 0; q < 4; q++) {
            __half2 t01 = __hadd2(p0[q], p1[q]);
            __half2 t23 = __hadd2(p2[q], p3[q]);
            float2 f01 = __half22float2(t01);
            float2 f23 = __half22float2(t23);
            acc[2 * q]     += f01.x + f23.x;
            acc[2 * q + 1] += f01.y + f23.y;
        }
    }
    for (; i < e; i++) {
        int c = g_col[i];
        uint4 v = hs4[c * 16 + l16];
        __half2* p = (__half2*)&v;
#pragma unroll
        for (int q = 0; q < 4; q++) {
            float2 f = __half22float2(p[q]);
            acc[2 * q] += f.x; acc[2 * q + 1] += f.y;
        }
    }
    float d = g_dis[node];
    const float4* b4 = (const float4*)bias;
    float4 b0 = b4[l16 * 2], b1 = b4[l16 * 2 + 1];
    float bb[8] = {b0.x, b0.y, b0.z, b0.w, b1.x, b1.y, b1.z, b1.w};
    __half2 o[4];
#pragma unroll
    for (int q = 0; q < 4; q++) {
        float r0 = acc[2 * q] * d + bb[2 * q];
        float r1 = acc[2 * q + 1] * d + bb[2 * q + 1];
        o[q] = __floats2half2_rn(d * fsilu(r0), d * fsilu(r1));
    }
    ((uint4*)out)[node * 16 + l16] = *(uint4*)o;
}

// ---------------- fused tail: hs3 = x~ @ W4, grid-sync, 3-wide agg -> out ---------
// s1 scratch is float4; phase 2 gathers with one LDG.128 per edge; re-zeroes g_deg.
#define TAIL_BLOCKS 592
__global__ __launch_bounds__(256) void k_tail(const __half* __restrict__ X,
                                              const float* __restrict__ W4,
                                              const float* __restrict__ bias,
                                              float* __restrict__ out, int n) {
    int t = threadIdx.x;
    int lane = t & 31;
    int nwarps = TAIL_BLOCKS * 8;
    for (int node = (blockIdx.x * 256 + t) >> 5; node < n; node += nwarps) {
        uint2 u = ((const uint2*)X)[node * 32 + lane];
        float2 p0 = __half22float2(*(__half2*)&u.x);
        float2 p1 = __half22float2(*(__half2*)&u.y);
        int k = lane * 4;
        float a0 = p0.x * W4[(k + 0) * 3 + 0] + p0.y * W4[(k + 1) * 3 + 0] +
                   p1.x * W4[(k + 2) * 3 + 0] + p1.y * W4[(k + 3) * 3 + 0];
        float a1 = p0.x * W4[(k + 0) * 3 + 1] + p0.y * W4[(k + 1) * 3 + 1] +
                   p1.x * W4[(k + 2) * 3 + 1] + p1.y * W4[(k + 3) * 3 + 1];
        float a2 = p0.x * W4[(k + 0) * 3 + 2] + p0.y * W4[(k + 1) * 3 + 2] +
                   p1.x * W4[(k + 2) * 3 + 2] + p1.y * W4[(k + 3) * 3 + 2];
        for (int off = 16; off; off >>= 1) {
            a0 += __shfl_xor_sync(0xFFFFFFFF, a0, off);
            a1 += __shfl_xor_sync(0xFFFFFFFF, a1, off);
            a2 += __shfl_xor_sync(0xFFFFFFFF, a2, off);
        }
        if (lane == 0) g_s1[node] = make_float4(a0, a1, a2, 0.0f);
    }
    __syncthreads();
    if (t == 0) {
        __threadfence();
        atomicAdd(&g_ct[1], 1);
        while (((volatile int*)&g_ct[1])[0] < TAIL_BLOCKS) {}
    }
    __syncthreads();
    __threadfence();
    float bb0 = bias[0], bb1 = bias[1], bb2 = bias[2];
    for (int node = blockIdx.x * 256 + t; node < n; node += TAIL_BLOCKS * 256) {
        float4 self = g_s1[node];
        float a0 = self.x, a1 = self.y, a2 = self.z;
        int s = g_rowptr[node], e = g_rowptr[node + 1];
        for (int i = s; i < e; i++) {
            float4 v = g_s1[g_col[i]];
            a0 += v.x; a1 += v.y; a2 += v.z;
        }
        float d = g_dis[node];
        out[node * 3 + 0] = a0 * d + bb0;
        out[node * 3 + 1] = a1 * d + bb1;
        out[node * 3 + 2] = a2 * d + bb2;
        g_deg[node] = 0;                 // clean for next launch
    }
}

// ---------------- host launch ----------------
extern "C" void kernel_launch(void* const* d_in, const int* in_sizes, int n_in,
                              void* d_out, int out_size) {
    const float* pos = (const float*)d_in[0];
    const int* ei_words = (const int*)d_in[1];
    const float* W[5]; const float* B[5];
    for (int l = 0; l < 5; l++) {
        W[l] = (const float*)d_in[2 + 2 * l];
        B[l] = (const float*)d_in[3 + 2 * l];
    }
    int N = in_sizes[0] / 3;        // 50000
    int E = in_sizes[1] / 2;        // 1000000

    __half *xbuf, *hsbuf, *bh3, *bl3;
    cudaGetSymbolAddress((void**)&xbuf, g_x);
    cudaGetSymbolAddress((void**)&hsbuf, g_hs);
    cudaGetSymbolAddress((void**)&bh3, g_Bh3);
    cudaGetSymbolAddress((void**)&bl3, g_Bl3);

    int NB = (N + 1023) / 1024;     // 49
    const int GEMM_SMEM = (2 * 128 * BPAD + 2 * 128 * APAD) * 2;   // 81920 bytes

    static int smem_set = 0;
    if (!smem_set) {
        cudaFuncSetAttribute(k_gemm128_tc,
                             cudaFuncAttributeMaxDynamicSharedMemorySize, GEMM_SMEM);
        smem_set = 1;
    }

    // front: counters + weight splits + degree count (deg zeroed by prior k_tail)
    k_front<<<(E + 255) / 256, 256>>>(ei_words, W[1], W[2], W[3], E);

    // fused scan (rowptr/cursor/dis/s1), CSR fill
    k_scan<<<NB, 1024>>>(pos, N);
    k_fill<<<(E + 255) / 256, 256>>>(ei_words, E);

    // layer 0 (fused 3-wide agg + dense W0 + bias + silu + dis fold) -> fp16 x~
    k_layer0<<<(N * 16 + 255) / 256, 256>>>(W[0], B[0], xbuf, N);

    // layers 1..3: TC GEMM then fp16 aggregation
    int gemm_blocks = NPAD / 128;            // 392
    int agg_blocks = (N * 16 + 255) / 256;   // 16 lanes per node
    for (int l = 1; l <= 3; l++) {
        k_gemm128_tc<<<gemm_blocks, 256, GEMM_SMEM>>>(xbuf, bh3 + (l - 1) * HD * HD,
                                                      bl3 + (l - 1) * HD * HD, hsbuf);
        k_agg128<<<agg_blocks, 256>>>(hsbuf, B[l], xbuf, N);
    }

    // fused tail: hs3 GEMM + grid sync + 3-wide aggregation -> out (+ deg re-zero)
    k_tail<<<TAIL_BLOCKS, 256>>>(xbuf, W[4], B[4], (float*)d_out, N);
}